// round 17
// baseline (speedup 1.0000x reference)
#include <cuda_runtime.h>
#include <cuda_bf16.h>
#include <stdint.h>

typedef unsigned long long ull;

// Problem constants
#define BB    16
#define NN    100000
#define CC    30
#define NC    (NN * CC)           // 3,000,000
#define TOT   (BB * NC)           // 48,000,000
#define PAIRS (BB * CC)           // 480
#define CAP   512                 // candidate buffer per (b,c)
#define PRE   200                 // PRE_NMS_TOPK
#define MAXDET 100
#define NWORDS 7                  // ceil(200/32)
#define NWP    8                  // padded row stride (words)
#define BOXPAD 224                // padded box count (NWORDS*32)
#define MPC    16                 // merge candidates per class
#define NTW   512                 // merge kernel block

// Overlapped scan+pair geometry: image = 750,000 float4 = 250 chunks x 3000.
#define CHUNKS_PER_IMG 250
#define CHUNK_F4       3000
#define GRID_SP        (BB * CHUNKS_PER_IMG)   // 4000 blocks, exact coverage

#define COLLECT_T    0.997f
#define SCORE_T      0.01f
#define NMS_T        0.5f

// Output layout (flattened float32 concat of the 5 outputs)
#define OUT_BOXES  0
#define OUT_SCORES (BB * MAXDET * 4)
#define OUT_LABELS (OUT_SCORES + BB * MAXDET)
#define OUT_ROT    (OUT_LABELS + BB * MAXDET)
#define OUT_TR     (OUT_ROT + BB * MAXDET * 3)

// Scratch (device globals; zero-initialized at module load)
__device__ ull      g_cand[PAIRS * CAP];
__device__ int      g_cnt[PAIRS];
__device__ ull      g_ckey[PAIRS * PRE];   // survivors by compacted rank
__device__ int      g_nidx[PAIRS * PRE];   // anchor index keyed by ORIGINAL rank
__device__ int      g_scnt[PAIRS];
__device__ unsigned g_img_done[BB];        // per-image scan-chunk counters

// ---------------------------------------------------------------------------
__device__ __forceinline__ void scan_proc(float4 v, int i4) {
    float m = fmaxf(fmaxf(v.x, v.y), fmaxf(v.z, v.w));
    if (m > COLLECT_T) {
        int base = i4 * 4;
        float vs[4] = {v.x, v.y, v.z, v.w};
#pragma unroll
        for (int k = 0; k < 4; k++) {
            float s = vs[k];
            if (s > COLLECT_T) {
                int i = base + k;
                int b = i / NC;
                int r = i - b * NC;
                int n = r / CC;
                int c = r - n * CC;
                int pair = b * CC + c;
                int pos = atomicAdd(&g_cnt[pair], 1);
                if (pos < CAP) {
                    g_cand[pair * CAP + pos] =
                        ((ull)__float_as_uint(s) << 32) | (unsigned)(~n);
                }
            }
        }
    }
}

// ---------------------------------------------------------------------------
// Hybrid bitonic sort of 512 u64 keys with 256 threads, 2 per thread
// (positions tid, tid+256). After return, v0 = key at rank tid (descending).
// Proven in R6-R8.
__device__ __forceinline__ void sort512h(ull& v0, ull& v1, ull* s_x, int tid) {
#pragma unroll
    for (int k2 = 2; k2 <= 512; k2 <<= 1) {
#pragma unroll
        for (int j = k2 >> 1; j > 0; j >>= 1) {
            if (j == 256) {
                if (v0 < v1) { ull t = v0; v0 = v1; v1 = t; }
            } else if (j >= 32) {
                s_x[tid] = v0; s_x[tid + 256] = v1;
                __syncthreads();
                ull o0 = s_x[tid ^ j];
                ull o1 = s_x[(tid ^ j) + 256];
                bool up = (tid & j) != 0;
                bool d0 = ((tid & k2) == 0);
                bool d1 = (((tid + 256) & k2) == 0);
                v0 = (up == d0) ? (v0 < o0 ? v0 : o0) : (v0 > o0 ? v0 : o0);
                v1 = (up == d1) ? (v1 < o1 ? v1 : o1) : (v1 > o1 ? v1 : o1);
                __syncthreads();
            } else {
                ull o0 = __shfl_xor_sync(0xFFFFFFFFu, v0, j);
                ull o1 = __shfl_xor_sync(0xFFFFFFFFu, v1, j);
                bool up = (tid & j) != 0;
                bool d0 = ((tid & k2) == 0);
                bool d1 = (((tid + 256) & k2) == 0);
                v0 = (up == d0) ? (v0 < o0 ? v0 : o0) : (v0 > o0 ? v0 : o0);
                v1 = (up == d1) ? (v1 < o1 ? v1 : o1) : (v1 > o1 ? v1 : o1);
            }
        }
    }
}

// ---------------------------------------------------------------------------
// Overlapped kernel: every block scans one 3000-float4 chunk; blocks < PAIRS
// then wait for their image's scan to complete and run the pair phase
// (top-200 sort + NMS + compaction). Pair (issue-bound, no DRAM) executes
// concurrently with remaining scan chunks (DRAM-bound, issue-idle).
__global__ void __launch_bounds__(256)
k_scanpair(const float* __restrict__ boxes, const float* __restrict__ cls) {
    __shared__ ull     s_x[CAP];
    __shared__ ull     s_keys[PRE];
    __shared__ float4  s_box[BOXPAD];
    __shared__ float   s_ar[BOXPAD];
    __shared__ unsigned s_sup[BOXPAD * NWP];
    __shared__ unsigned s_keep[NWORDS];
    __shared__ int     s_M;

    int tid = threadIdx.x;
    int blk = blockIdx.x;
    int img = blk / CHUNKS_PER_IMG;

    // ---------------- Scan phase: chunk blk = [blk*3000, blk*3000+3000) ----
    {
        const float4* c4 = reinterpret_cast<const float4*>(cls);
        int base = blk * CHUNK_F4;
        int end  = base + CHUNK_F4;
        int i = base + tid;
        for (; i + 768 < end; i += 1024) {
            float4 a = __ldg(&c4[i]);
            float4 b = __ldg(&c4[i + 256]);
            float4 c = __ldg(&c4[i + 512]);
            float4 d = __ldg(&c4[i + 768]);
            scan_proc(a, i);
            scan_proc(b, i + 256);
            scan_proc(c, i + 512);
            scan_proc(d, i + 768);
        }
        {   // predicated tail (<= 3 residual elements per thread, MLP-3)
            bool va = (i < end);
            bool vb = (i + 256 < end);
            bool vc = (i + 512 < end);
            float4 a, b, c;
            if (va) a = __ldg(&c4[i]);
            if (vb) b = __ldg(&c4[i + 256]);
            if (vc) c = __ldg(&c4[i + 512]);
            if (va) scan_proc(a, i);
            if (vb) scan_proc(b, i + 256);
            if (vc) scan_proc(c, i + 512);
        }
    }
    __threadfence();           // make this thread's scan writes visible
    __syncthreads();           // all threads of this block done + fenced
    if (tid == 0) atomicAdd(&g_img_done[img], 1u);

    if (blk >= PAIRS) return;

    // ---------------- Pair phase (blocks 0..479) ----------------
    int pair = blk;
    int b = pair / CC;
    int c = pair - b * CC;

    // Wait until image b fully scanned (release by producers above).
    if (tid == 0) {
        while (*((volatile unsigned*)&g_img_done[b]) < CHUNKS_PER_IMG)
            __nanosleep(64);
        __threadfence();       // acquire
    }
    __syncthreads();

    if (tid == 0) { s_M = g_cnt[pair]; g_cnt[pair] = 0; }
    __syncthreads();
    int M = s_M;

    if (M >= PRE && M <= CAP) {
        ull v0 = (tid < M)       ? g_cand[pair * CAP + tid]       : 0ULL;
        ull v1 = (tid + 256 < M) ? g_cand[pair * CAP + tid + 256] : 0ULL;
        sort512h(v0, v1, s_x, tid);
        if (tid < PRE) s_keys[tid] = v0;
    } else {
        // Exact fallback (statistically never taken): repeated bounded
        // argmax over the full column with the reference SCORE_T mask.
        ull prev = 0xFFFFFFFFFFFFFFFFULL;
        for (int k = 0; k < PRE; k++) {
            ull best = 0ULL;
            for (int n = tid; n < NN; n += 256) {
                float s = cls[(size_t)(b * NN + n) * CC + c];
                if (s > SCORE_T) {
                    ull key = ((ull)__float_as_uint(s) << 32) | (unsigned)(~n);
                    if (key < prev && key > best) best = key;
                }
            }
            s_x[tid] = best;
            __syncthreads();
            for (int st = 128; st > 0; st >>= 1) {
                if (tid < st && s_x[tid + st] > s_x[tid]) s_x[tid] = s_x[tid + st];
                __syncthreads();
            }
            if (tid == 0) s_keys[k] = s_x[0];
            prev = s_x[0];
            __syncthreads();
        }
    }
    __syncthreads();

    // Gather top-200 boxes; pad rows [PRE, BOXPAD) with inert zero-boxes.
    if (tid < BOXPAD) {
        ull key = (tid < PRE) ? s_keys[tid] : 0ULL;
        if (key != 0ULL) {
            unsigned n = ~(unsigned)(key & 0xFFFFFFFFULL);
            const float4* bp = reinterpret_cast<const float4*>(boxes);
            float4 bx = __ldg(&bp[(size_t)b * NN + n]);
            s_box[tid] = bx;
            s_ar[tid]  = fmaxf(bx.z - bx.x, 0.f) * fmaxf(bx.w - bx.y, 0.f);
        } else {
            s_box[tid] = make_float4(0.f, 0.f, 0.f, 0.f);
            s_ar[tid]  = 0.f;
        }
    }
    __syncthreads();

    // Suppression bit matrix, 448 (word, row-pair) tasks, division-free with
    // exact 1-ulp borderline re-resolution (see R16).
    for (int t = tid; t < 448; t += 256) {
        int w, p;
        if      (t < 16)  { w = 0; p = t; }
        else if (t < 48)  { w = 1; p = t - 16; }
        else if (t < 96)  { w = 2; p = t - 48; }
        else if (t < 160) { w = 3; p = t - 96; }
        else if (t < 240) { w = 4; p = t - 160; }
        else if (t < 336) { w = 5; p = t - 240; }
        else              { w = 6; p = t - 336; }
        int i0 = 2 * p, i1 = 2 * p + 1;
        float4 b0 = s_box[i0]; float a0 = s_ar[i0];
        float4 b1 = s_box[i1]; float a1 = s_ar[i1];
        unsigned wA0 = 0u, wB0 = 0u, wA1 = 0u, wB1 = 0u;
        int jbase = w * 32;
#pragma unroll 4
        for (int jj = 0; jj < 32; jj++) {
            int j = jbase + jj;
            float4 bj = s_box[j];
            float aj = s_ar[j];
            {
                float xx1 = fmaxf(b0.x, bj.x);
                float yy1 = fmaxf(b0.y, bj.y);
                float xx2 = fminf(b0.z, bj.z);
                float yy2 = fminf(b0.w, bj.w);
                float inter = fmaxf(xx2 - xx1, 0.f) * fmaxf(yy2 - yy1, 0.f);
                float u   = fmaxf(a0 + aj - inter, 1e-8f);
                float t05 = 0.5f * u;
                if (inter > t05) {
                    wA0 |= (1u << jj);
                    if (inter < t05 * 1.0000002f) wB0 |= (1u << jj);
                }
            }
            {
                float xx1 = fmaxf(b1.x, bj.x);
                float yy1 = fmaxf(b1.y, bj.y);
                float xx2 = fminf(b1.z, bj.z);
                float yy2 = fminf(b1.w, bj.w);
                float inter = fmaxf(xx2 - xx1, 0.f) * fmaxf(yy2 - yy1, 0.f);
                float u   = fmaxf(a1 + aj - inter, 1e-8f);
                float t05 = 0.5f * u;
                if (inter > t05) {
                    wA1 |= (1u << jj);
                    if (inter < t05 * 1.0000002f) wB1 |= (1u << jj);
                }
            }
        }
        while (wB0) {
            int jj = __ffs(wB0) - 1;
            wB0 &= wB0 - 1u;
            int j = jbase + jj;
            float4 bj = s_box[j];
            float xx1 = fmaxf(b0.x, bj.x), yy1 = fmaxf(b0.y, bj.y);
            float xx2 = fminf(b0.z, bj.z), yy2 = fminf(b0.w, bj.w);
            float inter = fmaxf(xx2 - xx1, 0.f) * fmaxf(yy2 - yy1, 0.f);
            float iou = inter / fmaxf(a0 + s_ar[j] - inter, 1e-8f);
            if (!(iou > NMS_T)) wA0 &= ~(1u << jj);
        }
        while (wB1) {
            int jj = __ffs(wB1) - 1;
            wB1 &= wB1 - 1u;
            int j = jbase + jj;
            float4 bj = s_box[j];
            float xx1 = fmaxf(b1.x, bj.x), yy1 = fmaxf(b1.y, bj.y);
            float xx2 = fminf(b1.z, bj.z), yy2 = fminf(b1.w, bj.w);
            float inter = fmaxf(xx2 - xx1, 0.f) * fmaxf(yy2 - yy1, 0.f);
            float iou = inter / fmaxf(a1 + s_ar[j] - inter, 1e-8f);
            if (!(iou > NMS_T)) wA1 &= ~(1u << jj);
        }
        if (w == (i0 >> 5)) {
            unsigned sh0 = (unsigned)(i0 & 31) + 1u;
            wA0 = (sh0 >= 32u) ? 0u : (wA0 & (0xFFFFFFFFu << sh0));
            unsigned sh1 = (unsigned)(i1 & 31) + 1u;
            wA1 = (sh1 >= 32u) ? 0u : (wA1 & (0xFFFFFFFFu << sh1));
        }
        s_sup[i0 * NWP + w] = wA0;
        s_sup[i1 * NWP + w] = wA1;
    }

    // Validity ballot (warps 0..6 cover 224 slots)
    {
        int w = tid >> 5, lane = tid & 31;
        bool val = (tid < PRE) && (s_keys[tid] != 0ULL);
        unsigned bal = __ballot_sync(0xFFFFFFFFu, val);
        if (w < NWORDS && lane == 0) s_keep[w] = bal;
    }
    __syncthreads();

    // Warp 0: chunked greedy NMS resolution + compaction.
    if (tid < 32) {
        int lane = tid;
        unsigned kw = (lane < NWORDS) ? s_keep[lane] : 0u;
        for (int cch = 0; cch < NWORDS; cch++) {
            unsigned cur = __shfl_sync(0xFFFFFFFFu, kw, cch);
            if (lane == 0) {
                unsigned d[32];
#pragma unroll
                for (int jj = 0; jj < 32; jj++)
                    d[jj] = s_sup[(cch * 32 + jj) * NWP + cch];
#pragma unroll
                for (int jj = 0; jj < 32; jj++)
                    if ((cur >> jj) & 1u) cur &= ~d[jj];
            }
            cur = __shfl_sync(0xFFFFFFFFu, cur, 0);
            if (lane == cch) kw = cur;
            if (lane > cch && lane < NWORDS) {
                unsigned acc = 0u;
#pragma unroll
                for (int jj = 0; jj < 32; jj++)
                    if ((cur >> jj) & 1u) acc |= s_sup[(cch * 32 + jj) * NWP + lane];
                kw &= ~acc;
            }
        }
        // Compaction in rank order.
        int offset = 0;
        for (int chunk = 0; chunk < NWORDS; chunk++) {
            unsigned bits = __shfl_sync(0xFFFFFFFFu, kw, chunk);
            int j = chunk * 32 + lane;
            bool kp = (bits >> lane) & 1u;
            if (kp) {
                int rank = offset + __popc(bits & ((1u << lane) - 1u));
                ull key = s_keys[j];
                unsigned n   = ~(unsigned)(key & 0xFFFFFFFFULL);
                unsigned pos = (unsigned)(c * PRE + j);
                g_ckey[pair * PRE + rank] =
                    (key & 0xFFFFFFFF00000000ULL) | (ull)(0xFFFFFFFFu - pos);
                g_nidx[pair * PRE + j] = (int)n;
            }
            offset += __popc(bits);
        }
        if (lane == 0) g_scnt[pair] = offset;
    }
}

// ---------------------------------------------------------------------------
// Bitonic sort of 512 u64 keys with 512 threads, one per thread (ping-pong,
// one sync per smem stage). Used by k_merge.
__device__ __forceinline__ void sort512w(ull& v, ull* bufA, ull* bufB, int tid) {
    int pp = 0;
#pragma unroll
    for (int k2 = 2; k2 <= 512; k2 <<= 1) {
#pragma unroll
        for (int j = k2 >> 1; j > 0; j >>= 1) {
            bool up = (tid & j) != 0;
            bool d  = ((tid & k2) == 0);
            ull o;
            if (j >= 32) {
                ull* buf = pp ? bufB : bufA;
                buf[tid] = v;
                __syncthreads();
                o = buf[tid ^ j];
                pp ^= 1;
            } else {
                o = __shfl_xor_sync(0xFFFFFFFFu, v, j);
            }
            v = (up == d) ? (v < o ? v : o) : (v > o ? v : o);
        }
    }
}

// ---------------------------------------------------------------------------
// Pass 3: per image — exact top-100 via sort of first-16-per-class survivor
// keys (with exact saturation check + rare exact fallback), then output.
// Also resets g_img_done for graph replay (runs strictly after k_scanpair).
__global__ void __launch_bounds__(NTW)
k_merge(const float* __restrict__ boxes, const float* __restrict__ rot,
        const float* __restrict__ tr, float* __restrict__ out) {
    __shared__ ull   s_x[CAP];
    __shared__ ull   s_y[CAP];
    __shared__ int   s_scnt[CC];
    __shared__ int   s_ccnt[CC];
    __shared__ int   s_flag;
    __shared__ int   s_idx[MAXDET];
    __shared__ float s_score[MAXDET];
    __shared__ int   s_lab[MAXDET];

    int tid = threadIdx.x;
    int b   = blockIdx.x;

    if (tid == 0) { s_flag = 0; g_img_done[b] = 0u; }
    if (tid < CC) { s_scnt[tid] = g_scnt[b * CC + tid]; s_ccnt[tid] = 0; }
    if (tid < MAXDET) s_idx[tid] = -1;
    __syncthreads();

    // Candidate keys: slot tid -> class tid/16, compacted rank tid%16.
    ull v = 0ULL;
    if (tid < CC * MPC) {
        int cc = tid >> 4, j = tid & 15;
        if (j < s_scnt[cc]) v = g_ckey[(b * CC + cc) * PRE + j];
    }
    sort512w(v, s_x, s_y, tid);
    __syncthreads();
    s_x[tid] = v;                 // descending
    __syncthreads();

    // Saturation check
    if (tid < MAXDET) {
        ull key = s_x[tid];
        if (key != 0ULL) {
            unsigned pos = 0xFFFFFFFFu - (unsigned)(key & 0xFFFFFFFFULL);
            atomicAdd(&s_ccnt[pos / PRE], 1);
        }
    }
    __syncthreads();
    if (tid < CC && s_ccnt[tid] >= MPC && s_scnt[tid] > MPC) s_flag = 1;
    __syncthreads();

    if (!s_flag) {
        if (tid < MAXDET) {
            ull key = s_x[tid];
            if (key != 0ULL) {
                unsigned pos = 0xFFFFFFFFu - (unsigned)(key & 0xFFFFFFFFULL);
                int cc = pos / PRE;
                int jo = pos - cc * PRE;
                s_score[tid] = __uint_as_float((unsigned)(key >> 32));
                s_lab[tid]   = cc;
                s_idx[tid]   = g_nidx[(b * CC + cc) * PRE + jo];
            }
        }
    } else if (tid < 32) {
        // Exact fallback: serial 30-way merge over full survivor lists.
        int lane = tid;
        int cnt = 0, ptr = 0;
        ull head = 0ULL;
        if (lane < CC) {
            cnt = s_scnt[lane];
            head = (ptr < cnt) ? g_ckey[(b * CC + lane) * PRE + 0] : 0ULL;
        }
        for (int t = 0; t < MAXDET; t++) {
            ull m = head;
#pragma unroll
            for (int o = 16; o; o >>= 1) {
                ull other = __shfl_xor_sync(0xFFFFFFFFu, m, o);
                if (other > m) m = other;
            }
            if (m == 0ULL) break;
            if (head == m) {
                unsigned pos = 0xFFFFFFFFu - (unsigned)(m & 0xFFFFFFFFULL);
                int jo = pos - lane * PRE;
                s_score[t] = __uint_as_float((unsigned)(m >> 32));
                s_lab[t]   = lane;
                s_idx[t]   = g_nidx[(b * CC + lane) * PRE + jo];
                ptr++;
                head = (ptr < cnt) ? g_ckey[(b * CC + lane) * PRE + ptr] : 0ULL;
            }
        }
    }
    __syncthreads();

    // Output
    for (int t = tid; t < MAXDET; t += NTW) {
        int idx = s_idx[t];
        if (idx >= 0) {
            const float4* bp = reinterpret_cast<const float4*>(boxes);
            float4 bx = __ldg(&bp[(size_t)b * NN + idx]);
            out[OUT_BOXES + (b * MAXDET + t) * 4 + 0] = bx.x;
            out[OUT_BOXES + (b * MAXDET + t) * 4 + 1] = bx.y;
            out[OUT_BOXES + (b * MAXDET + t) * 4 + 2] = bx.z;
            out[OUT_BOXES + (b * MAXDET + t) * 4 + 3] = bx.w;
            out[OUT_SCORES + b * MAXDET + t] = s_score[t];
            out[OUT_LABELS + b * MAXDET + t] = (float)s_lab[t];
            size_t rb = ((size_t)b * NN + idx) * 3;
#pragma unroll
            for (int k = 0; k < 3; k++) {
                out[OUT_ROT + (b * MAXDET + t) * 3 + k] = __ldg(&rot[rb + k]);
                out[OUT_TR  + (b * MAXDET + t) * 3 + k] = __ldg(&tr[rb + k]);
            }
        } else {
#pragma unroll
            for (int k = 0; k < 4; k++)
                out[OUT_BOXES + (b * MAXDET + t) * 4 + k] = -1.0f;
            out[OUT_SCORES + b * MAXDET + t] = -1.0f;
            out[OUT_LABELS + b * MAXDET + t] = -1.0f;
#pragma unroll
            for (int k = 0; k < 3; k++) {
                out[OUT_ROT + (b * MAXDET + t) * 3 + k] = -1.0f;
                out[OUT_TR  + (b * MAXDET + t) * 3 + k] = -1.0f;
            }
        }
    }
}

// ---------------------------------------------------------------------------
extern "C" void kernel_launch(void* const* d_in, const int* in_sizes, int n_in,
                              void* d_out, int out_size) {
    const float* boxes = (const float*)d_in[0];
    const float* cls   = (const float*)d_in[1];
    const float* rot   = (const float*)d_in[2];
    const float* tr    = (const float*)d_in[3];
    float* out = (float*)d_out;

    k_scanpair<<<GRID_SP, 256>>>(boxes, cls);
    k_merge<<<BB, NTW>>>(boxes, rot, tr, out);
}